// round 1
// baseline (speedup 1.0000x reference)
#include <cuda_runtime.h>
#include <math.h>

#define N_NODES 50000
#define N_EDGES 800000
#define NH 256
#define EH 64
#define HT 128   // NH/2
#define HR 32    // EH/2
#define EPSV 0.01f
#define NSTEPS 10

// Scratch (static __device__ arrays — allocation-free per harness rules)
__device__ float  g_hsd[N_NODES * 64];   // interleaved: [node*64 + j] = hs_j (j<32), hd_{j-32} (j>=32)
__device__ float2 g_ep[N_EDGES];         // (edge_len, 2*step_size)
__device__ float  g_aggr[N_NODES * 3];

__device__ __forceinline__ float leaky(float x) { return x > 0.f ? x : 0.01f * x; }

// ---------------------------------------------------------------------------
// Kernel A: torsion head. 16 nodes / block, 128 threads.
// h = leaky(emb @ Wt1 + bt1); t = h @ Wt2 + bt2; -> (rho, phi, theta)
// ---------------------------------------------------------------------------
__global__ void __launch_bounds__(128) torsion_kernel(
    const float* __restrict__ node_emb,
    const float* __restrict__ Wt1, const float* __restrict__ bt1,
    const float* __restrict__ Wt2, const float* __restrict__ bt2,
    float* __restrict__ out_tors)
{
    __shared__ float emb[16][NH];     // 16KB
    __shared__ float hact[16][HT];    // 8KB
    __shared__ float tvec[16][3];

    const int nb = blockIdx.x * 16;
    const int t  = threadIdx.x;

    // stage 16 node rows (4096 floats) coalesced
    const float* src = node_emb + (size_t)nb * NH;
    for (int i = t; i < 16 * NH; i += 128) ((float*)emb)[i] = src[i];
    __syncthreads();

    // thread t owns hidden column t for all 16 nodes
    float acc[16];
    const float b = bt1[t];
    #pragma unroll
    for (int n = 0; n < 16; n++) acc[n] = b;
    for (int k = 0; k < NH; k++) {
        const float w = Wt1[k * HT + t];
        #pragma unroll
        for (int n = 0; n < 16; n++) acc[n] += emb[n][k] * w;
    }
    #pragma unroll
    for (int n = 0; n < 16; n++) hact[n][t] = leaky(acc[n]);
    __syncthreads();

    // tiny second GEMM: 16 nodes x 3 components
    if (t < 48) {
        const int n = t / 3, c = t % 3;
        float s = bt2[c];
        #pragma unroll 8
        for (int j = 0; j < HT; j++) s += hact[n][j] * Wt2[j * 3 + c];
        tvec[n][c] = s;
    }
    __syncthreads();

    if (t < 16) {
        const float t0 = tvec[t][0], t1 = tvec[t][1], t2 = tvec[t][2];
        const float rho = sqrtf(t0 * t0 + t1 * t1 + t2 * t2);
        const float inv = 1.f / rho;
        const float n0 = t0 * inv, n1 = t1 * inv, n2 = t2 * inv;
        const float half_pi = 1.57079632679489662f;
        const float theta = (fabsf(n0) > fabsf(n1)) ? atan2f(n1, n0)
                                                    : (half_pi - atan2f(n0, n1));
        const float cz  = fminf(fmaxf(n2, -1.f + EPSV), 1.f - EPSV);
        const float phi = acosf(cz);
        const int node = nb + t;
        out_tors[node * 3 + 0] = rho;
        out_tors[node * 3 + 1] = phi;
        out_tors[node * 3 + 2] = theta;
    }
}

// ---------------------------------------------------------------------------
// Kernel B: hs = emb @ Ws, hd = emb @ Wd  (Ws = Wr1[64:320], Wd = Wr1[320:576])
// 16 nodes / block, 256 threads. thread = (sub 0..3, col 0..63); 4 nodes each.
// ---------------------------------------------------------------------------
__global__ void __launch_bounds__(256) hsd_kernel(
    const float* __restrict__ node_emb,
    const float* __restrict__ Wr1)
{
    __shared__ float emb[16][NH];  // 16KB
    const int nb  = blockIdx.x * 16;
    const int t   = threadIdx.x;
    const int c   = t & 63;
    const int sub = t >> 6;

    const float* src = node_emb + (size_t)nb * NH;
    for (int i = t; i < 16 * NH; i += 256) ((float*)emb)[i] = src[i];
    __syncthreads();

    // column pointer into Wr1: Ws block rows [64,320), Wd block rows [320,576)
    const float* wcol = (c < 32) ? (Wr1 + EH * HR + c)
                                 : (Wr1 + (EH + NH) * HR + (c - 32));
    float acc[4] = {0.f, 0.f, 0.f, 0.f};
    for (int k = 0; k < NH; k++) {
        const float w = wcol[k * HR];
        #pragma unroll
        for (int n = 0; n < 4; n++) acc[n] += emb[sub * 4 + n][k] * w;
    }
    #pragma unroll
    for (int n = 0; n < 4; n++) {
        const int node = nb + sub * 4 + n;
        g_hsd[(size_t)node * 64 + c] = acc[n];
    }
}

// ---------------------------------------------------------------------------
// Kernel C: per-edge refiner MLP. 8 edges / block (warp per edge), 256 threads.
// h = leaky(edge_emb @ We + hs[src] + hd[dest] + br1); out = h @ Wr2 + br2
// -> edge_len = softplus(out0 + 1), step2 = 2*sigmoid(out1 - 2)
// ---------------------------------------------------------------------------
__global__ void __launch_bounds__(256) edge_mlp_kernel(
    const float* __restrict__ edge_emb,
    const float* __restrict__ Wr1, const float* __restrict__ br1,
    const float* __restrict__ Wr2, const float* __restrict__ br2,
    const int* __restrict__ ei)
{
    __shared__ float Wes[EH][HR];   // 8KB  (We = Wr1[0:64])
    __shared__ float eemb[8][EH];   // 2KB
    __shared__ float w2[HR * 2];
    __shared__ float br1s[HR];

    const int t = threadIdx.x;
    for (int i = t; i < EH * HR; i += 256) ((float*)Wes)[i] = Wr1[i];
    if (t < 64) w2[t] = Wr2[t];
    if (t < 32) br1s[t] = br1[t];

    const int e0 = blockIdx.x * 8;
    const float* esrc = edge_emb + (size_t)e0 * EH;
    for (int i = t; i < 8 * EH; i += 256) ((float*)eemb)[i] = esrc[i];
    __syncthreads();

    const int w = t >> 5, j = t & 31;
    const int e = e0 + w;
    const int s = ei[e];
    const int d = ei[N_EDGES + e];

    float acc = br1s[j] + g_hsd[(size_t)s * 64 + j] + g_hsd[(size_t)d * 64 + 32 + j];
    #pragma unroll
    for (int k = 0; k < EH; k++) acc += eemb[w][k] * Wes[k][j];
    const float h = leaky(acc);

    float r0 = h * w2[j * 2 + 0];
    float r1 = h * w2[j * 2 + 1];
    #pragma unroll
    for (int off = 16; off; off >>= 1) {
        r0 += __shfl_xor_sync(0xFFFFFFFFu, r0, off);
        r1 += __shfl_xor_sync(0xFFFFFFFFu, r1, off);
    }
    if (j == 0) {
        const float o0 = r0 + br2[0] + 1.0f;
        const float el = (o0 > 20.f) ? o0 : log1pf(expf(o0));   // softplus
        const float o1 = r1 + br2[1] - 2.0f;
        const float st = 1.f / (1.f + expf(-o1));               // sigmoid
        g_ep[e] = make_float2(el, 2.f * st);
    }
}

// ---------------------------------------------------------------------------
// init: coords <- cart_init (in d_out), aggr <- 0
// ---------------------------------------------------------------------------
__global__ void init_kernel(const float* __restrict__ cart, float* __restrict__ coords)
{
    const int i = blockIdx.x * blockDim.x + threadIdx.x;
    if (i < N_NODES * 3) { coords[i] = cart[i]; g_aggr[i] = 0.f; }
}

// ---------------------------------------------------------------------------
// Kernel D: per-edge force + atomic scatter into g_aggr[dest]
// ---------------------------------------------------------------------------
__global__ void __launch_bounds__(256) force_kernel(
    const float* __restrict__ coords, const int* __restrict__ ei)
{
    const int e = blockIdx.x * blockDim.x + threadIdx.x;
    if (e >= N_EDGES) return;
    const int s = ei[e];
    const int d = ei[N_EDGES + e];
    const float sx = coords[s * 3 + 0], sy = coords[s * 3 + 1], sz = coords[s * 3 + 2];
    const float dx = coords[d * 3 + 0], dy = coords[d * 3 + 1], dz = coords[d * 3 + 2];
    const float fx = dx - sx, fy = dy - sy, fz = dz - sz;
    const float dist = sqrtf(fx * fx + fy * fy + fz * fz);
    const float2 p = g_ep[e];                 // (edge_len, 2*step)
    const float f = p.y * (p.x - dist) / (dist + EPSV);
    atomicAdd(&g_aggr[d * 3 + 0], f * fx);
    atomicAdd(&g_aggr[d * 3 + 1], f * fy);
    atomicAdd(&g_aggr[d * 3 + 2], f * fz);
}

// ---------------------------------------------------------------------------
// Kernel E: node update: coords += aggr/||aggr|| * min(||aggr||+eps, 0.5)... per ref:
// an = ||aggr|| + eps; coords += aggr/an * min(an, 0.5); aggr <- 0
// ---------------------------------------------------------------------------
__global__ void __launch_bounds__(256) update_kernel(float* __restrict__ coords)
{
    const int n = blockIdx.x * blockDim.x + threadIdx.x;
    if (n >= N_NODES) return;
    const float ax = g_aggr[n * 3 + 0];
    const float ay = g_aggr[n * 3 + 1];
    const float az = g_aggr[n * 3 + 2];
    const float an = sqrtf(ax * ax + ay * ay + az * az) + EPSV;
    const float sc = fminf(an, 0.5f) / an;
    coords[n * 3 + 0] += ax * sc;
    coords[n * 3 + 1] += ay * sc;
    coords[n * 3 + 2] += az * sc;
    g_aggr[n * 3 + 0] = 0.f;
    g_aggr[n * 3 + 1] = 0.f;
    g_aggr[n * 3 + 2] = 0.f;
}

// ---------------------------------------------------------------------------
extern "C" void kernel_launch(void* const* d_in, const int* in_sizes, int n_in,
                              void* d_out, int out_size)
{
    const float* node_emb = (const float*)d_in[0];
    const float* edge_emb = (const float*)d_in[1];
    const float* cart     = (const float*)d_in[2];
    const float* Wt1      = (const float*)d_in[3];
    const float* bt1      = (const float*)d_in[4];
    const float* Wt2      = (const float*)d_in[5];
    const float* bt2      = (const float*)d_in[6];
    const float* Wr1      = (const float*)d_in[7];
    const float* br1      = (const float*)d_in[8];
    const float* Wr2      = (const float*)d_in[9];
    const float* br2      = (const float*)d_in[10];
    const int*   ei       = (const int*)d_in[11];

    float* coords   = (float*)d_out;                 // [0 : 150000)
    float* out_tors = (float*)d_out + N_NODES * 3;   // [150000 : 300000)

    // independent precompute
    torsion_kernel<<<N_NODES / 16, 128>>>(node_emb, Wt1, bt1, Wt2, bt2, out_tors);
    hsd_kernel<<<(N_NODES + 15) / 16, 256>>>(node_emb, Wr1);
    edge_mlp_kernel<<<N_EDGES / 8, 256>>>(edge_emb, Wr1, br1, Wr2, br2, ei);
    init_kernel<<<(N_NODES * 3 + 255) / 256, 256>>>(cart, coords);

    // 10 refinement steps
    for (int it = 0; it < NSTEPS; it++) {
        force_kernel<<<(N_EDGES + 255) / 256, 256>>>(coords, ei);
        update_kernel<<<(N_NODES + 255) / 256, 256>>>(coords);
    }
}

// round 2
// speedup vs baseline: 1.8515x; 1.8515x over previous
#include <cuda_runtime.h>
#include <math.h>

#define N_NODES 50000
#define N_EDGES 800000
#define NH 256
#define EH 64
#define HT 128   // NH/2
#define HR 32    // EH/2
#define EPSV 0.01f
#define NSTEPS 10
#define NBLK_SCAN 196   // ceil(50000/256)

// ---------------- static scratch (allocation-free) ----------------
__device__ float  g_hsd[(size_t)N_NODES * 64];   // [node*64+j]: j<32 hs, j>=32 hd
__device__ float  g_coordsB[N_NODES * 3];        // ping-pong buffer
__device__ int    g_cnt[N_NODES];
__device__ int    g_base[N_NODES];
__device__ int    g_fill[N_NODES];
__device__ int    g_bsum[256];
__device__ int    g_src_csr[N_EDGES];
__device__ float2 g_ep_csr[N_EDGES];             // (edge_len, 2*step)

__device__ __forceinline__ float leaky(float x) { return x > 0.f ? x : 0.01f * x; }

__device__ __forceinline__ unsigned long long pk(float lo, float hi) {
    unsigned long long r;
    asm("mov.b64 %0, {%1, %2};" : "=l"(r) : "f"(lo), "f"(hi));
    return r;
}
__device__ __forceinline__ void upk(unsigned long long v, float& lo, float& hi) {
    asm("mov.b64 {%0, %1}, %2;" : "=f"(lo), "=f"(hi) : "l"(v));
}
// packed fp32x2 FMA: acc = a*b + acc (exact fp32, 2 MACs/instr)
__device__ __forceinline__ void fma2(unsigned long long& acc, unsigned long long a,
                                     unsigned long long b) {
    asm("fma.rn.f32x2 %0, %1, %2, %0;" : "+l"(acc) : "l"(a), "l"(b));
}

// ---------------------------------------------------------------------------
// Fused node kernel: torsion MLP + hs/hd projections. 16 nodes/block.
// 96 threads: t<64 torsion (owns hidden cols t, t+64); t in [64,96) hsd
// (owns hs col c and hd col c). emb staged TRANSPOSED: embT[k][n], n contig.
// ---------------------------------------------------------------------------
__global__ void __launch_bounds__(96) node_kernel(
    const float* __restrict__ node_emb,
    const float* __restrict__ Wt1, const float* __restrict__ bt1,
    const float* __restrict__ Wt2, const float* __restrict__ bt2,
    const float* __restrict__ Wr1,
    float* __restrict__ out_tors)
{
    __shared__ __align__(16) float embT[NH * 16];   // [k][n], 16KB
    __shared__ float hact[16][HT + 1];              // padded vs bank conflicts
    __shared__ float tvec[16][3];

    const int t  = threadIdx.x;
    const int nb = blockIdx.x * 16;

    const float* src = node_emb + (size_t)nb * NH;
    for (int i = t; i < 16 * NH; i += 96)
        embT[(i & (NH - 1)) * 16 + (i >> 8)] = src[i];
    __syncthreads();

    unsigned long long accA[8], accB[8];
    if (t < 64) {
        // torsion: hidden cols t and t+64
        const float b0 = bt1[t], b1 = bt1[t + 64];
        #pragma unroll
        for (int m = 0; m < 8; m++) { accA[m] = pk(b0, b0); accB[m] = pk(b1, b1); }
        const float* wp = Wt1 + t;
        #pragma unroll 2
        for (int k = 0; k < NH; k++) {
            const float w0 = wp[k * HT];
            const float w1 = wp[k * HT + 64];
            const unsigned long long ww0 = pk(w0, w0);
            const unsigned long long ww1 = pk(w1, w1);
            const ulonglong2* r = (const ulonglong2*)(embT + k * 16);
            const ulonglong2 p0 = r[0], p1 = r[1], p2 = r[2], p3 = r[3];
            fma2(accA[0], p0.x, ww0); fma2(accA[1], p0.y, ww0);
            fma2(accA[2], p1.x, ww0); fma2(accA[3], p1.y, ww0);
            fma2(accA[4], p2.x, ww0); fma2(accA[5], p2.y, ww0);
            fma2(accA[6], p3.x, ww0); fma2(accA[7], p3.y, ww0);
            fma2(accB[0], p0.x, ww1); fma2(accB[1], p0.y, ww1);
            fma2(accB[2], p1.x, ww1); fma2(accB[3], p1.y, ww1);
            fma2(accB[4], p2.x, ww1); fma2(accB[5], p2.y, ww1);
            fma2(accB[6], p3.x, ww1); fma2(accB[7], p3.y, ww1);
        }
        #pragma unroll
        for (int m = 0; m < 8; m++) {
            float lo, hi;
            upk(accA[m], lo, hi);
            hact[2 * m][t] = leaky(lo); hact[2 * m + 1][t] = leaky(hi);
            upk(accB[m], lo, hi);
            hact[2 * m][t + 64] = leaky(lo); hact[2 * m + 1][t + 64] = leaky(hi);
        }
    } else {
        // hsd: hs col c (Ws = Wr1[64:320]), hd col c (Wd = Wr1[320:576])
        const int c = t - 64;
        #pragma unroll
        for (int m = 0; m < 8; m++) { accA[m] = 0ull; accB[m] = 0ull; }
        const float* wp0 = Wr1 + EH * HR + c;
        const float* wp1 = Wr1 + (EH + NH) * HR + c;
        #pragma unroll 2
        for (int k = 0; k < NH; k++) {
            const float w0 = wp0[k * HR];
            const float w1 = wp1[k * HR];
            const unsigned long long ww0 = pk(w0, w0);
            const unsigned long long ww1 = pk(w1, w1);
            const ulonglong2* r = (const ulonglong2*)(embT + k * 16);
            const ulonglong2 p0 = r[0], p1 = r[1], p2 = r[2], p3 = r[3];
            fma2(accA[0], p0.x, ww0); fma2(accA[1], p0.y, ww0);
            fma2(accA[2], p1.x, ww0); fma2(accA[3], p1.y, ww0);
            fma2(accA[4], p2.x, ww0); fma2(accA[5], p2.y, ww0);
            fma2(accA[6], p3.x, ww0); fma2(accA[7], p3.y, ww0);
            fma2(accB[0], p0.x, ww1); fma2(accB[1], p0.y, ww1);
            fma2(accB[2], p1.x, ww1); fma2(accB[3], p1.y, ww1);
            fma2(accB[4], p2.x, ww1); fma2(accB[5], p2.y, ww1);
            fma2(accB[6], p3.x, ww1); fma2(accB[7], p3.y, ww1);
        }
        #pragma unroll
        for (int m = 0; m < 8; m++) {
            float lo, hi;
            upk(accA[m], lo, hi);
            g_hsd[(size_t)(nb + 2 * m) * 64 + c]     = lo;
            g_hsd[(size_t)(nb + 2 * m + 1) * 64 + c] = hi;
            upk(accB[m], lo, hi);
            g_hsd[(size_t)(nb + 2 * m) * 64 + 32 + c]     = lo;
            g_hsd[(size_t)(nb + 2 * m + 1) * 64 + 32 + c] = hi;
        }
    }
    __syncthreads();

    // layer 2: 16 nodes x 3 components
    if (t < 48) {
        const int n = t / 3, c = t % 3;
        float s = bt2[c];
        #pragma unroll 8
        for (int j = 0; j < HT; j++) s += hact[n][j] * Wt2[j * 3 + c];
        tvec[n][c] = s;
    }
    __syncthreads();

    if (t < 16) {
        const float t0 = tvec[t][0], t1 = tvec[t][1], t2 = tvec[t][2];
        const float rho = sqrtf(t0 * t0 + t1 * t1 + t2 * t2);
        const float inv = 1.f / rho;
        const float n0 = t0 * inv, n1 = t1 * inv, n2 = t2 * inv;
        const float half_pi = 1.57079632679489662f;
        const float theta = (fabsf(n0) > fabsf(n1)) ? atan2f(n1, n0)
                                                    : (half_pi - atan2f(n0, n1));
        const float cz  = fminf(fmaxf(n2, -1.f + EPSV), 1.f - EPSV);
        const float phi = acosf(cz);
        const int node = nb + t;
        out_tors[node * 3 + 0] = rho;
        out_tors[node * 3 + 1] = phi;
        out_tors[node * 3 + 2] = theta;
    }
}

// ---------------------------------------------------------------------------
// Edge MLP + CSR scatter. 128 edges/block, 256 threads (8 warps x 16 edges).
// Lane j owns hidden unit j; accumulators packed as f32x2 pairs over edges.
// Epilogue writes (edge_len, 2*step) directly into CSR position by dest.
// ---------------------------------------------------------------------------
#define E_PAD 132   // 64-edge... row stride for 128 edges + pad (16B-aligned, low conflict)
__global__ void __launch_bounds__(256) edge_kernel(
    const float* __restrict__ edge_emb,
    const float* __restrict__ Wr1, const float* __restrict__ br1,
    const float* __restrict__ Wr2, const float* __restrict__ br2,
    const int* __restrict__ ei)
{
    __shared__ __align__(16) float Wes[EH * HR];      // 8KB (We = Wr1[0:64])
    __shared__ __align__(16) float eT[EH * E_PAD];    // [k][e], 33.8KB
    __shared__ float br1s[HR], w2a[HR], w2b[HR];

    const int t = threadIdx.x;
    for (int i = t; i < EH * HR; i += 256) Wes[i] = Wr1[i];
    if (t < HR) { br1s[t] = br1[t]; w2a[t] = Wr2[t * 2]; w2b[t] = Wr2[t * 2 + 1]; }

    const int e_base = blockIdx.x * 128;
    const float* es = edge_emb + (size_t)e_base * EH;
    for (int i = t; i < 128 * EH; i += 256)
        eT[(i & 63) * E_PAD + (i >> 6)] = es[i];
    __syncthreads();

    const int j  = t & 31;
    const int e0 = (t >> 5) * 16;   // this warp's 16 edges

    unsigned long long acc[8];
    #pragma unroll
    for (int m = 0; m < 8; m++) acc[m] = 0ull;

    #pragma unroll 4
    for (int k = 0; k < EH; k++) {
        const float w = Wes[k * HR + j];
        const unsigned long long ww = pk(w, w);
        const ulonglong2* r = (const ulonglong2*)(eT + k * E_PAD + e0);
        const ulonglong2 p0 = r[0], p1 = r[1], p2 = r[2], p3 = r[3];
        fma2(acc[0], p0.x, ww); fma2(acc[1], p0.y, ww);
        fma2(acc[2], p1.x, ww); fma2(acc[3], p1.y, ww);
        fma2(acc[4], p2.x, ww); fma2(acc[5], p2.y, ww);
        fma2(acc[6], p3.x, ww); fma2(acc[7], p3.y, ww);
    }
    float av[16];
    #pragma unroll
    for (int m = 0; m < 8; m++) upk(acc[m], av[2 * m], av[2 * m + 1]);

    const float bj = br1s[j], wa = w2a[j], wb = w2b[j];
    float my0 = 0.f, my1 = 0.f;
    int my_s = 0, my_d = 0;

    #pragma unroll
    for (int idx = 0; idx < 16; idx++) {
        const int e = e_base + e0 + idx;
        const int s = ei[e];
        const int d = ei[N_EDGES + e];
        float hh = av[idx] + bj + g_hsd[(size_t)s * 64 + j]
                 + g_hsd[(size_t)d * 64 + 32 + j];
        hh = leaky(hh);
        float r0 = hh * wa, r1 = hh * wb;
        #pragma unroll
        for (int o = 16; o; o >>= 1) {
            r0 += __shfl_xor_sync(0xFFFFFFFFu, r0, o);
            r1 += __shfl_xor_sync(0xFFFFFFFFu, r1, o);
        }
        if (j == idx) { my0 = r0; my1 = r1; my_s = s; my_d = d; }
    }

    if (j < 16) {
        const float o0 = my0 + br2[0] + 1.0f;
        const float el = (o0 > 20.f) ? o0 : log1pf(expf(o0));
        const float o1 = my1 + br2[1] - 2.0f;
        const float st = 1.f / (1.f + expf(-o1));
        const int pos = atomicAdd(&g_fill[my_d], 1);
        g_src_csr[pos] = my_s;
        g_ep_csr[pos]  = make_float2(el, 2.f * st);
    }
}

// ---------------------------------------------------------------------------
// init: coords <- cart_init; cnt <- 0
// ---------------------------------------------------------------------------
__global__ void init_kernel(const float* __restrict__ cart, float* __restrict__ coords)
{
    const int i = blockIdx.x * blockDim.x + threadIdx.x;
    if (i < N_NODES * 3) coords[i] = cart[i];
    if (i < N_NODES) g_cnt[i] = 0;
}

__global__ void hist_kernel(const int* __restrict__ ei)
{
    const int e = blockIdx.x * blockDim.x + threadIdx.x;
    if (e < N_EDGES) atomicAdd(&g_cnt[ei[N_EDGES + e]], 1);
}

// 3-phase exclusive scan of g_cnt -> g_base (and g_fill)
__global__ void scan1_kernel()
{
    __shared__ int s[256];
    const int t  = threadIdx.x;
    const int gi = blockIdx.x * 256 + t;
    const int v  = (gi < N_NODES) ? g_cnt[gi] : 0;
    s[t] = v; __syncthreads();
    for (int o = 1; o < 256; o <<= 1) {
        const int x = (t >= o) ? s[t - o] : 0;
        __syncthreads();
        s[t] += x;
        __syncthreads();
    }
    if (gi < N_NODES) g_base[gi] = s[t] - v;   // exclusive within block
    if (t == 255) g_bsum[blockIdx.x] = s[255];
}
__global__ void scan2_kernel()
{
    __shared__ int s[256];
    const int t = threadIdx.x;
    const int v = (t < NBLK_SCAN) ? g_bsum[t] : 0;
    s[t] = v; __syncthreads();
    for (int o = 1; o < 256; o <<= 1) {
        const int x = (t >= o) ? s[t - o] : 0;
        __syncthreads();
        s[t] += x;
        __syncthreads();
    }
    g_bsum[t] = s[t] - v;
}
__global__ void scan3_kernel()
{
    const int gi = blockIdx.x * 256 + threadIdx.x;
    if (gi < N_NODES) {
        const int b = g_base[gi] + g_bsum[gi >> 8];
        g_base[gi] = b;
        g_fill[gi] = b;
    }
}

// ---------------------------------------------------------------------------
// Fused refine step: per node, gather incoming edges from CSR, no atomics.
// 4 lanes per node; double-buffered coords (cin -> cout).
// ---------------------------------------------------------------------------
__global__ void __launch_bounds__(256) refine_kernel(
    const float* __restrict__ cin, float* __restrict__ cout)
{
    const int g = blockIdx.x * 256 + threadIdx.x;
    const int n = g >> 2, l = g & 3;
    if (n >= N_NODES) return;
    const int b  = g_base[n];
    const int cn = g_cnt[n];
    const float cx = cin[n * 3 + 0], cy = cin[n * 3 + 1], cz = cin[n * 3 + 2];
    float fx = 0.f, fy = 0.f, fz = 0.f;
    for (int i = b + l; i < b + cn; i += 4) {
        const int s = g_src_csr[i];
        const float2 p = g_ep_csr[i];
        const float ddx = cx - cin[s * 3 + 0];
        const float ddy = cy - cin[s * 3 + 1];
        const float ddz = cz - cin[s * 3 + 2];
        const float dist = sqrtf(ddx * ddx + ddy * ddy + ddz * ddz);
        const float f = p.y * (p.x - dist) / (dist + EPSV);
        fx += f * ddx; fy += f * ddy; fz += f * ddz;
    }
    fx += __shfl_xor_sync(0xFFFFFFFFu, fx, 1);
    fy += __shfl_xor_sync(0xFFFFFFFFu, fy, 1);
    fz += __shfl_xor_sync(0xFFFFFFFFu, fz, 1);
    fx += __shfl_xor_sync(0xFFFFFFFFu, fx, 2);
    fy += __shfl_xor_sync(0xFFFFFFFFu, fy, 2);
    fz += __shfl_xor_sync(0xFFFFFFFFu, fz, 2);
    if (l == 0) {
        const float an = sqrtf(fx * fx + fy * fy + fz * fz) + EPSV;
        const float sc = fminf(an, 0.5f) / an;
        cout[n * 3 + 0] = cx + fx * sc;
        cout[n * 3 + 1] = cy + fy * sc;
        cout[n * 3 + 2] = cz + fz * sc;
    }
}

// ---------------------------------------------------------------------------
extern "C" void kernel_launch(void* const* d_in, const int* in_sizes, int n_in,
                              void* d_out, int out_size)
{
    const float* node_emb = (const float*)d_in[0];
    const float* edge_emb = (const float*)d_in[1];
    const float* cart     = (const float*)d_in[2];
    const float* Wt1      = (const float*)d_in[3];
    const float* bt1      = (const float*)d_in[4];
    const float* Wt2      = (const float*)d_in[5];
    const float* bt2      = (const float*)d_in[6];
    const float* Wr1      = (const float*)d_in[7];
    const float* br1      = (const float*)d_in[8];
    const float* Wr2      = (const float*)d_in[9];
    const float* br2      = (const float*)d_in[10];
    const int*   ei       = (const int*)d_in[11];

    float* coordsA  = (float*)d_out;                 // final output region
    float* out_tors = (float*)d_out + N_NODES * 3;

    float* coordsB = nullptr;
    cudaGetSymbolAddress((void**)&coordsB, g_coordsB);

    // fused node MLPs (torsion + hs/hd)
    node_kernel<<<N_NODES / 16, 96>>>(node_emb, Wt1, bt1, Wt2, bt2, Wr1, out_tors);

    // coords init + CSR build (counting sort by dest)
    init_kernel<<<(N_NODES * 3 + 255) / 256, 256>>>(cart, coordsA);
    hist_kernel<<<(N_EDGES + 255) / 256, 256>>>(ei);
    scan1_kernel<<<NBLK_SCAN, 256>>>();
    scan2_kernel<<<1, 256>>>();
    scan3_kernel<<<NBLK_SCAN, 256>>>();

    // edge MLP, scattering results into CSR order
    edge_kernel<<<N_EDGES / 128, 256>>>(edge_emb, Wr1, br1, Wr2, br2, ei);

    // 10 refinement steps, ping-pong buffers; even count ends in coordsA=d_out
    const int rblocks = (N_NODES * 4 + 255) / 256;
    for (int it = 0; it < NSTEPS; it++) {
        const float* cin  = (it & 1) ? coordsB : coordsA;
        float*       cout = (it & 1) ? coordsA : coordsB;
        refine_kernel<<<rblocks, 256>>>(cin, cout);
    }
}

// round 4
// speedup vs baseline: 1.9537x; 1.0552x over previous
#include <cuda_runtime.h>
#include <math.h>

#define N_NODES 50000
#define N_EDGES 800000
#define NH 256
#define EH 64
#define HT 128   // NH/2
#define HR 32    // EH/2
#define EPSV 0.01f
#define NSTEPS 10

// ---------------- static scratch (allocation-free) ----------------
__device__ float  g_hsd[(size_t)N_NODES * 64];   // [node*64+j]: j<32 hs, j>=32 hd
__device__ float4 g_cA[N_NODES];                 // coords ping (x,y,z,0)
__device__ float4 g_cB[N_NODES];                 // coords pong
__device__ int    g_cnt[N_NODES];
__device__ int2   g_seg[N_NODES];                // (base, cnt)
__device__ int    g_fill[N_NODES];
__device__ int    g_alloc;
__device__ float4 g_csr[N_EDGES];                // (src_bits, edge_len, 2*step, 0)

__device__ __forceinline__ float leaky(float x) { return x > 0.f ? x : 0.01f * x; }

__device__ __forceinline__ unsigned long long pk(float lo, float hi) {
    unsigned long long r;
    asm("mov.b64 %0, {%1, %2};" : "=l"(r) : "f"(lo), "f"(hi));
    return r;
}
__device__ __forceinline__ void upk(unsigned long long v, float& lo, float& hi) {
    asm("mov.b64 {%0, %1}, %2;" : "=f"(lo), "=f"(hi) : "l"(v));
}
// packed fp32x2 FMA: acc = a*b + acc (exact fp32, 2 MACs/instr)
__device__ __forceinline__ void fma2(unsigned long long& acc, unsigned long long a,
                                     unsigned long long b) {
    asm("fma.rn.f32x2 %0, %1, %2, %0;" : "+l"(acc) : "l"(a), "l"(b));
}

// ---------------------------------------------------------------------------
// init: coords(float4) <- cart_init; cnt <- 0; alloc <- 0
// ---------------------------------------------------------------------------
__global__ void __launch_bounds__(256) init_kernel(const float* __restrict__ cart)
{
    const int i = blockIdx.x * blockDim.x + threadIdx.x;
    if (i < N_NODES) {
        g_cA[i] = make_float4(cart[i * 3 + 0], cart[i * 3 + 1], cart[i * 3 + 2], 0.f);
        g_cnt[i] = 0;
    }
    if (i == 0) g_alloc = 0;
}

__global__ void __launch_bounds__(256) hist_kernel(const int* __restrict__ ei)
{
    const int e = blockIdx.x * blockDim.x + threadIdx.x;
    if (e < N_EDGES) atomicAdd(&g_cnt[ei[N_EDGES + e]], 1);
}

// ---------------------------------------------------------------------------
// alloc: disjoint CSR segment bases (order irrelevant). Warp scan + block
// aggregation + one global atomic per block.
// ---------------------------------------------------------------------------
__global__ void __launch_bounds__(256) alloc_kernel()
{
    __shared__ int wsum[8];
    __shared__ int sbase;
    const int t    = threadIdx.x;
    const int lane = t & 31;
    const int wrp  = t >> 5;
    const int n    = blockIdx.x * 256 + t;
    const int c    = (n < N_NODES) ? g_cnt[n] : 0;

    // warp inclusive scan of c
    int pre = c;
    #pragma unroll
    for (int o = 1; o < 32; o <<= 1) {
        const int v = __shfl_up_sync(0xFFFFFFFFu, pre, o);
        if (lane >= o) pre += v;
    }
    if (lane == 31) wsum[wrp] = pre;
    __syncthreads();
    if (t == 0) {
        int s = 0;
        #pragma unroll
        for (int w = 0; w < 8; w++) { const int tmp = wsum[w]; wsum[w] = s; s += tmp; }
        sbase = atomicAdd(&g_alloc, s);
    }
    __syncthreads();
    if (n < N_NODES) {
        const int b = sbase + wsum[wrp] + pre - c;
        g_seg[n]  = make_int2(b, c);
        g_fill[n] = b;
    }
}

// ---------------------------------------------------------------------------
// Fused node kernel: torsion MLP + hs/hd projections. 16 nodes/block.
// 96 threads: t<64 torsion (hidden cols t, t+64); t in [64,96) hs/hd col c.
// emb staged TRANSPOSED: embT[k][n], nodes contiguous -> LDS.128 + f32x2 FMA.
// ---------------------------------------------------------------------------
__global__ void __launch_bounds__(96) node_kernel(
    const float* __restrict__ node_emb,
    const float* __restrict__ Wt1, const float* __restrict__ bt1,
    const float* __restrict__ Wt2, const float* __restrict__ bt2,
    const float* __restrict__ Wr1,
    float* __restrict__ out_tors)
{
    __shared__ __align__(16) float embT[NH * 16];   // [k][n], 16KB
    __shared__ float hact[16][HT + 1];
    __shared__ float tvec[16][3];

    const int t  = threadIdx.x;
    const int nb = blockIdx.x * 16;

    const float* src = node_emb + (size_t)nb * NH;
    for (int i = t; i < 16 * NH; i += 96)
        embT[(i & (NH - 1)) * 16 + (i >> 8)] = src[i];
    __syncthreads();

    unsigned long long accA[8], accB[8];
    if (t < 64) {
        const float b0 = bt1[t], b1 = bt1[t + 64];
        #pragma unroll
        for (int m = 0; m < 8; m++) { accA[m] = pk(b0, b0); accB[m] = pk(b1, b1); }
        const float* wp = Wt1 + t;
        #pragma unroll 2
        for (int k = 0; k < NH; k++) {
            const float w0 = wp[k * HT];
            const float w1 = wp[k * HT + 64];
            const unsigned long long ww0 = pk(w0, w0);
            const unsigned long long ww1 = pk(w1, w1);
            const ulonglong2* r = (const ulonglong2*)(embT + k * 16);
            const ulonglong2 p0 = r[0], p1 = r[1], p2 = r[2], p3 = r[3];
            fma2(accA[0], p0.x, ww0); fma2(accA[1], p0.y, ww0);
            fma2(accA[2], p1.x, ww0); fma2(accA[3], p1.y, ww0);
            fma2(accA[4], p2.x, ww0); fma2(accA[5], p2.y, ww0);
            fma2(accA[6], p3.x, ww0); fma2(accA[7], p3.y, ww0);
            fma2(accB[0], p0.x, ww1); fma2(accB[1], p0.y, ww1);
            fma2(accB[2], p1.x, ww1); fma2(accB[3], p1.y, ww1);
            fma2(accB[4], p2.x, ww1); fma2(accB[5], p2.y, ww1);
            fma2(accB[6], p3.x, ww1); fma2(accB[7], p3.y, ww1);
        }
        #pragma unroll
        for (int m = 0; m < 8; m++) {
            float lo, hi;
            upk(accA[m], lo, hi);
            hact[2 * m][t] = leaky(lo); hact[2 * m + 1][t] = leaky(hi);
            upk(accB[m], lo, hi);
            hact[2 * m][t + 64] = leaky(lo); hact[2 * m + 1][t + 64] = leaky(hi);
        }
    } else {
        const int c = t - 64;
        #pragma unroll
        for (int m = 0; m < 8; m++) { accA[m] = 0ull; accB[m] = 0ull; }
        const float* wp0 = Wr1 + EH * HR + c;
        const float* wp1 = Wr1 + (EH + NH) * HR + c;
        #pragma unroll 2
        for (int k = 0; k < NH; k++) {
            const float w0 = wp0[k * HR];
            const float w1 = wp1[k * HR];
            const unsigned long long ww0 = pk(w0, w0);
            const unsigned long long ww1 = pk(w1, w1);
            const ulonglong2* r = (const ulonglong2*)(embT + k * 16);
            const ulonglong2 p0 = r[0], p1 = r[1], p2 = r[2], p3 = r[3];
            fma2(accA[0], p0.x, ww0); fma2(accA[1], p0.y, ww0);
            fma2(accA[2], p1.x, ww0); fma2(accA[3], p1.y, ww0);
            fma2(accA[4], p2.x, ww0); fma2(accA[5], p2.y, ww0);
            fma2(accA[6], p3.x, ww0); fma2(accA[7], p3.y, ww0);
            fma2(accB[0], p0.x, ww1); fma2(accB[1], p0.y, ww1);
            fma2(accB[2], p1.x, ww1); fma2(accB[3], p1.y, ww1);
            fma2(accB[4], p2.x, ww1); fma2(accB[5], p2.y, ww1);
            fma2(accB[6], p3.x, ww1); fma2(accB[7], p3.y, ww1);
        }
        #pragma unroll
        for (int m = 0; m < 8; m++) {
            float lo, hi;
            upk(accA[m], lo, hi);
            g_hsd[(size_t)(nb + 2 * m) * 64 + c]     = lo;
            g_hsd[(size_t)(nb + 2 * m + 1) * 64 + c] = hi;
            upk(accB[m], lo, hi);
            g_hsd[(size_t)(nb + 2 * m) * 64 + 32 + c]     = lo;
            g_hsd[(size_t)(nb + 2 * m + 1) * 64 + 32 + c] = hi;
        }
    }
    __syncthreads();

    if (t < 48) {
        const int n = t / 3, c = t % 3;
        float s = bt2[c];
        #pragma unroll 8
        for (int j = 0; j < HT; j++) s += hact[n][j] * Wt2[j * 3 + c];
        tvec[n][c] = s;
    }
    __syncthreads();

    if (t < 16) {
        const float t0 = tvec[t][0], t1 = tvec[t][1], t2 = tvec[t][2];
        const float rho = sqrtf(t0 * t0 + t1 * t1 + t2 * t2);
        const float inv = 1.f / rho;
        const float n0 = t0 * inv, n1 = t1 * inv, n2 = t2 * inv;
        const float half_pi = 1.57079632679489662f;
        const float theta = (fabsf(n0) > fabsf(n1)) ? atan2f(n1, n0)
                                                    : (half_pi - atan2f(n0, n1));
        const float cz  = fminf(fmaxf(n2, -1.f + EPSV), 1.f - EPSV);
        const float phi = acosf(cz);
        const int node = nb + t;
        out_tors[node * 3 + 0] = rho;
        out_tors[node * 3 + 1] = phi;
        out_tors[node * 3 + 2] = theta;
    }
}

// ---------------------------------------------------------------------------
// Edge MLP + CSR scatter. 128 edges/block, 256 threads (8 warps x 16 edges).
// Writes one float4 CSR record per edge: (src_bits, edge_len, 2*step, 0).
// ---------------------------------------------------------------------------
#define E_PAD 132
__global__ void __launch_bounds__(256) edge_kernel(
    const float* __restrict__ edge_emb,
    const float* __restrict__ Wr1, const float* __restrict__ br1,
    const float* __restrict__ Wr2, const float* __restrict__ br2,
    const int* __restrict__ ei)
{
    __shared__ __align__(16) float Wes[EH * HR];
    __shared__ __align__(16) float eT[EH * E_PAD];
    __shared__ float br1s[HR], w2a[HR], w2b[HR];

    const int t = threadIdx.x;
    for (int i = t; i < EH * HR; i += 256) Wes[i] = Wr1[i];
    if (t < HR) { br1s[t] = br1[t]; w2a[t] = Wr2[t * 2]; w2b[t] = Wr2[t * 2 + 1]; }

    const int e_base = blockIdx.x * 128;
    const float* es = edge_emb + (size_t)e_base * EH;
    for (int i = t; i < 128 * EH; i += 256)
        eT[(i & 63) * E_PAD + (i >> 6)] = es[i];
    __syncthreads();

    const int j  = t & 31;
    const int e0 = (t >> 5) * 16;

    unsigned long long acc[8];
    #pragma unroll
    for (int m = 0; m < 8; m++) acc[m] = 0ull;

    #pragma unroll 4
    for (int k = 0; k < EH; k++) {
        const float w = Wes[k * HR + j];
        const unsigned long long ww = pk(w, w);
        const ulonglong2* r = (const ulonglong2*)(eT + k * E_PAD + e0);
        const ulonglong2 p0 = r[0], p1 = r[1], p2 = r[2], p3 = r[3];
        fma2(acc[0], p0.x, ww); fma2(acc[1], p0.y, ww);
        fma2(acc[2], p1.x, ww); fma2(acc[3], p1.y, ww);
        fma2(acc[4], p2.x, ww); fma2(acc[5], p2.y, ww);
        fma2(acc[6], p3.x, ww); fma2(acc[7], p3.y, ww);
    }
    float av[16];
    #pragma unroll
    for (int m = 0; m < 8; m++) upk(acc[m], av[2 * m], av[2 * m + 1]);

    const float bj = br1s[j], wa = w2a[j], wb = w2b[j];
    float my0 = 0.f, my1 = 0.f;
    int my_s = 0, my_d = 0;

    #pragma unroll
    for (int idx = 0; idx < 16; idx++) {
        const int e = e_base + e0 + idx;
        const int s = ei[e];
        const int d = ei[N_EDGES + e];
        float hh = av[idx] + bj + g_hsd[(size_t)s * 64 + j]
                 + g_hsd[(size_t)d * 64 + 32 + j];
        hh = leaky(hh);
        float r0 = hh * wa, r1 = hh * wb;
        #pragma unroll
        for (int o = 16; o; o >>= 1) {
            r0 += __shfl_xor_sync(0xFFFFFFFFu, r0, o);
            r1 += __shfl_xor_sync(0xFFFFFFFFu, r1, o);
        }
        if (j == idx) { my0 = r0; my1 = r1; my_s = s; my_d = d; }
    }

    if (j < 16) {
        const float o0 = my0 + br2[0] + 1.0f;
        const float el = (o0 > 20.f) ? o0 : log1pf(expf(o0));
        const float o1 = my1 + br2[1] - 2.0f;
        const float st = 1.f / (1.f + expf(-o1));
        const int pos = atomicAdd(&g_fill[my_d], 1);
        g_csr[pos] = make_float4(__int_as_float(my_s), el, 2.f * st, 0.f);
    }
}

// ---------------------------------------------------------------------------
// Refine step: per node gather from CSR (no atomics). 4 lanes/node.
// One LDG.128 per CSR record + one LDG.128 coord gather. LAST writes packed
// float3 directly into d_out.
// ---------------------------------------------------------------------------
template <bool LAST>
__global__ void __launch_bounds__(256) refine_kernel(
    const float4* __restrict__ cin, float4* __restrict__ cout,
    float* __restrict__ out3)
{
    const int g = blockIdx.x * 256 + threadIdx.x;
    const int n = g >> 2, l = g & 3;
    if (n >= N_NODES) return;
    const int2 seg = g_seg[n];
    const float4 c = cin[n];
    float fx = 0.f, fy = 0.f, fz = 0.f;
    const int end = seg.x + seg.y;
    #pragma unroll 2
    for (int i = seg.x + l; i < end; i += 4) {
        const float4 e = __ldg(&g_csr[i]);
        const int s = __float_as_int(e.x);
        const float4 cs = __ldg(&cin[s]);
        const float ddx = c.x - cs.x;
        const float ddy = c.y - cs.y;
        const float ddz = c.z - cs.z;
        const float dist = sqrtf(ddx * ddx + ddy * ddy + ddz * ddz);
        const float f = e.z * (e.y - dist) / (dist + EPSV);
        fx += f * ddx; fy += f * ddy; fz += f * ddz;
    }
    fx += __shfl_xor_sync(0xFFFFFFFFu, fx, 1);
    fy += __shfl_xor_sync(0xFFFFFFFFu, fy, 1);
    fz += __shfl_xor_sync(0xFFFFFFFFu, fz, 1);
    fx += __shfl_xor_sync(0xFFFFFFFFu, fx, 2);
    fy += __shfl_xor_sync(0xFFFFFFFFu, fy, 2);
    fz += __shfl_xor_sync(0xFFFFFFFFu, fz, 2);
    if (l == 0) {
        const float an = sqrtf(fx * fx + fy * fy + fz * fz) + EPSV;
        const float sc = fminf(an, 0.5f) / an;
        if (LAST) {
            out3[n * 3 + 0] = c.x + fx * sc;
            out3[n * 3 + 1] = c.y + fy * sc;
            out3[n * 3 + 2] = c.z + fz * sc;
        } else {
            cout[n] = make_float4(c.x + fx * sc, c.y + fy * sc, c.z + fz * sc, 0.f);
        }
    }
}

// ---------------------------------------------------------------------------
extern "C" void kernel_launch(void* const* d_in, const int* in_sizes, int n_in,
                              void* d_out, int out_size)
{
    const float* node_emb = (const float*)d_in[0];
    const float* edge_emb = (const float*)d_in[1];
    const float* cart     = (const float*)d_in[2];
    const float* Wt1      = (const float*)d_in[3];
    const float* bt1      = (const float*)d_in[4];
    const float* Wt2      = (const float*)d_in[5];
    const float* bt2      = (const float*)d_in[6];
    const float* Wr1      = (const float*)d_in[7];
    const float* br1      = (const float*)d_in[8];
    const float* Wr2      = (const float*)d_in[9];
    const float* br2      = (const float*)d_in[10];
    const int*   ei       = (const int*)d_in[11];

    float* out_coords = (float*)d_out;
    float* out_tors   = (float*)d_out + N_NODES * 3;

    float4 *cA = nullptr, *cB = nullptr;
    cudaGetSymbolAddress((void**)&cA, g_cA);
    cudaGetSymbolAddress((void**)&cB, g_cB);

    // 1-3: coord init + histogram + CSR allocation
    init_kernel<<<(N_NODES + 255) / 256, 256>>>(cart);
    hist_kernel<<<(N_EDGES + 255) / 256, 256>>>(ei);
    alloc_kernel<<<(N_NODES + 255) / 256, 256>>>();

    // 4: fused node MLPs (torsion + hs/hd)  [ncu capture target]
    node_kernel<<<N_NODES / 16, 96>>>(node_emb, Wt1, bt1, Wt2, bt2, Wr1, out_tors);

    // 5: edge MLP -> CSR records
    edge_kernel<<<N_EDGES / 128, 256>>>(edge_emb, Wr1, br1, Wr2, br2, ei);

    // 6-15: refinement (ping-pong float4; last iter writes packed to d_out)
    const int rblocks = (N_NODES * 4 + 255) / 256;
    for (int it = 0; it < NSTEPS; it++) {
        const float4* cin = (it & 1) ? cB : cA;
        float4*      cout = (it & 1) ? cA : cB;
        if (it == NSTEPS - 1)
            refine_kernel<true><<<rblocks, 256>>>(cin, cout, out_coords);
        else
            refine_kernel<false><<<rblocks, 256>>>(cin, cout, nullptr);
    }
}